// round 14
// baseline (speedup 1.0000x reference)
#include <cuda_runtime.h>
#include <cuda_fp16.h>

// DiffeomorphicTransform: scaling-and-squaring, 7 steps.
// R9: R8 structure (planar fp32 carry + 8B fp16 mirror gathers, fused-scale
//     first step, mirror-only convert) + issue-side micro-opts:
//   - 2D grid (blockIdx -> y,z): no div/mod, no bounds guard
//   - rf in __constant__ (cudaMemcpyToSymbolAsync D2D, graph-capturable)
//   - incremental gather base addressing (selects instead of IMAD chains)

#define DD 128
#define HH 160
#define WW 128
#define NVOX (DD * HH * WW)          // 2,621,440
#define NELEM (3 * NVOX)

__device__ float g_fA[NELEM];        // planar fp32 carry
__device__ float g_fB[NELEM];
__device__ uint2 g_hA[NVOX];         // fp16 mirror: half2(x,y), half2(z,0)
__device__ uint2 g_hB[NVOX];

__constant__ float c_rf;

__device__ __forceinline__ uint2 pack_h(float x, float y, float z) {
    __half2 xy = __floats2half2_rn(x, y);
    __half2 z0 = __floats2half2_rn(z, 0.0f);
    uint2 r;
    r.x = *reinterpret_cast<unsigned int*>(&xy);
    r.y = *reinterpret_cast<unsigned int*>(&z0);
    return r;
}

__device__ __forceinline__ float3 unpack_h(uint2 raw) {
    __half2 xy = *reinterpret_cast<__half2*>(&raw.x);
    __half2 z0 = *reinterpret_cast<__half2*>(&raw.y);
    float2 fxy = __half22float2(xy);
    return make_float3(fxy.x, fxy.y, __low2float(z0));
}

// velocity -> fp16 mirror of flow0 = vel/128 (mirror only)
__global__ void __launch_bounds__(256) convert_kernel(
    const float* __restrict__ vel, uint2* __restrict__ outh)
{
    int v = blockIdx.x * blockDim.x + threadIdx.x;
    const float s = 1.0f / 128.0f;
    outh[v] = pack_h(vel[v] * s, vel[NVOX + v] * s, vel[2 * NVOX + v] * s);
}

template <bool FIRST, bool LAST>
__global__ void __launch_bounds__(256) step_kernel(
    const float* __restrict__ fin,     // planar fp32 carry (velocity if FIRST)
    const uint2* __restrict__ hin,     // fp16 mirror (gather source)
    float* __restrict__ fout,          // planar fp32 (dst buffer or d_out)
    uint2* __restrict__ houth)         // fp16 mirror out (unused on last)
{
    // grid = (HH/2, DD), block = 256 = two x-rows
    const int x = threadIdx.x & (WW - 1);
    const int y = (blockIdx.x << 1) | (threadIdx.x >> 7);
    const int z = blockIdx.y;
    const int v = (z * HH + y) * WW + x;

    const float rf = c_rf;
    const float sx = rf * 0.5f * (float)(WW - 1);
    const float sy = rf * 0.5f * (float)(HH - 1);
    const float sz = rf * 0.5f * (float)(DD - 1);

    float fx = __ldcs(&fin[v]);
    float fy = __ldcs(&fin[NVOX + v]);
    float fz = __ldcs(&fin[2 * NVOX + v]);
    if (FIRST) {
        const float s = 1.0f / 128.0f;
        fx *= s; fy *= s; fz *= s;
    }

    float ix = fmaf(fx, sx, (float)x);
    float iy = fmaf(fy, sy, (float)y);
    float iz = fmaf(fz, sz, (float)z);
    ix = fminf(fmaxf(ix, 0.0f), (float)(WW - 1));
    iy = fminf(fmaxf(iy, 0.0f), (float)(HH - 1));
    iz = fminf(fmaxf(iz, 0.0f), (float)(DD - 1));

    const float x0f = floorf(ix), y0f = floorf(iy), z0f = floorf(iz);
    const float wx = ix - x0f, wy = iy - y0f, wz = iz - z0f;
    const int x0 = (int)x0f, y0 = (int)y0f, z0 = (int)z0f;
    const int x1 = min(x0 + 1, WW - 1);

    // incremental bases: dy/dz are 0 or a constant stride (select, no IMAD)
    const int dy = (y0 < HH - 1) ? WW : 0;
    const int dz = (z0 < DD - 1) ? (HH * WW) : 0;
    const int b00 = (z0 * HH + y0) * WW;
    const int b01 = b00 + dy;
    const int b10 = b00 + dz;
    const int b11 = b10 + dy;

    const float3 c000 = unpack_h(__ldg(&hin[b00 + x0]));
    const float3 c001 = unpack_h(__ldg(&hin[b00 + x1]));
    const float3 c010 = unpack_h(__ldg(&hin[b01 + x0]));
    const float3 c011 = unpack_h(__ldg(&hin[b01 + x1]));
    const float3 c100 = unpack_h(__ldg(&hin[b10 + x0]));
    const float3 c101 = unpack_h(__ldg(&hin[b10 + x1]));
    const float3 c110 = unpack_h(__ldg(&hin[b11 + x0]));
    const float3 c111 = unpack_h(__ldg(&hin[b11 + x1]));

    const float owx = 1.0f - wx, owy = 1.0f - wy, owz = 1.0f - wz;
    const float w00 = owz * owy, w01 = owz * wy, w10 = wz * owy, w11 = wz * wy;
    const float w000 = w00 * owx, w001 = w00 * wx;
    const float w010 = w01 * owx, w011 = w01 * wx;
    const float w100 = w10 * owx, w101 = w10 * wx;
    const float w110 = w11 * owx, w111 = w11 * wx;

    float rx = fx, ry = fy, rz = fz;
    rx = fmaf(w000, c000.x, rx); ry = fmaf(w000, c000.y, ry); rz = fmaf(w000, c000.z, rz);
    rx = fmaf(w001, c001.x, rx); ry = fmaf(w001, c001.y, ry); rz = fmaf(w001, c001.z, rz);
    rx = fmaf(w010, c010.x, rx); ry = fmaf(w010, c010.y, ry); rz = fmaf(w010, c010.z, rz);
    rx = fmaf(w011, c011.x, rx); ry = fmaf(w011, c011.y, ry); rz = fmaf(w011, c011.z, rz);
    rx = fmaf(w100, c100.x, rx); ry = fmaf(w100, c100.y, ry); rz = fmaf(w100, c100.z, rz);
    rx = fmaf(w101, c101.x, rx); ry = fmaf(w101, c101.y, ry); rz = fmaf(w101, c101.z, rz);
    rx = fmaf(w110, c110.x, rx); ry = fmaf(w110, c110.y, ry); rz = fmaf(w110, c110.z, rz);
    rx = fmaf(w111, c111.x, rx); ry = fmaf(w111, c111.y, ry); rz = fmaf(w111, c111.z, rz);

    if (LAST) {
        fout[v]            = rx;
        fout[NVOX + v]     = ry;
        fout[2 * NVOX + v] = rz;
    } else {
        __stcs(&fout[v],            rx);
        __stcs(&fout[NVOX + v],     ry);
        __stcs(&fout[2 * NVOX + v], rz);
        houth[v] = pack_h(rx, ry, rz);   // mirror: keep cached (hot data)
    }
}

extern "C" void kernel_launch(void* const* d_in, const int* in_sizes, int n_in,
                              void* d_out, int out_size) {
    (void)in_sizes; (void)n_in; (void)out_size;
    const float* velocity = (const float*)d_in[0];
    const float* rf       = (const float*)d_in[2];
    float* out            = (float*)d_out;

    float *fA, *fB;
    uint2 *hA, *hB;
    cudaGetSymbolAddress((void**)&fA, g_fA);
    cudaGetSymbolAddress((void**)&fB, g_fB);
    cudaGetSymbolAddress((void**)&hA, g_hA);
    cudaGetSymbolAddress((void**)&hB, g_hB);

    // rf (device scalar) -> __constant__, async D2D (graph-capturable)
    cudaMemcpyToSymbolAsync(c_rf, rf, sizeof(float), 0, cudaMemcpyDeviceToDevice);

    const int T = 256;
    const dim3 G2(HH / 2, DD);        // 80 x 128 = 10240 blocks of 256

    convert_kernel<<<NVOX / T, T>>>(velocity, hA);

    // step 1: fin = velocity (scaled in-kernel), mirror = hA, out -> fA/hB
    step_kernel<true, false><<<G2, T>>>(velocity, hA, fA, hB);

    // steps 2..6
    float* src = fA;  uint2* hsrc = hB;
    float* dst = fB;  uint2* hdst = hA;
    for (int it = 0; it < 5; it++) {
        step_kernel<false, false><<<G2, T>>>(src, hsrc, dst, hdst);
        float* t1 = src; src = dst; dst = t1;
        uint2* t2 = hsrc; hsrc = hdst; hdst = t2;
    }
    // step 7 -> d_out
    step_kernel<false, true><<<G2, T>>>(src, hsrc, out, nullptr);
}

// round 17
// speedup vs baseline: 1.5390x; 1.5390x over previous
#include <cuda_runtime.h>
#include <cuda_fp16.h>

// DiffeomorphicTransform: scaling-and-squaring, 7 steps.
// R10: exact revert to R8 (best: 195.9us) + ONE change: rf scalar moved to
//      __constant__ via graph-capturable async D2D copy (was per-thread __ldg).
//      R9's bundled 2D-grid/select-addressing changes are dropped (regression).

#define DD 128
#define HH 160
#define WW 128
#define NVOX (DD * HH * WW)          // 2,621,440
#define NELEM (3 * NVOX)

// Ping-pong scratch (no cudaMalloc allowed).
__device__ float g_fA[NELEM];        // planar fp32 carry
__device__ float g_fB[NELEM];
__device__ uint2 g_hA[NVOX];         // fp16 mirror: half2(x,y), half2(z,0)
__device__ uint2 g_hB[NVOX];

__constant__ float c_rf;

__device__ __forceinline__ uint2 pack_h(float x, float y, float z) {
    __half2 xy = __floats2half2_rn(x, y);
    __half2 z0 = __floats2half2_rn(z, 0.0f);
    uint2 r;
    r.x = *reinterpret_cast<unsigned int*>(&xy);
    r.y = *reinterpret_cast<unsigned int*>(&z0);
    return r;
}

__device__ __forceinline__ float3 unpack_h(uint2 raw) {
    __half2 xy = *reinterpret_cast<__half2*>(&raw.x);
    __half2 z0 = *reinterpret_cast<__half2*>(&raw.y);
    float2 fxy = __half22float2(xy);
    return make_float3(fxy.x, fxy.y, __low2float(z0));
}

// velocity -> fp16 mirror of flow0 = vel/128 (mirror only; no fp32 write)
__global__ void __launch_bounds__(256) convert_kernel(
    const float* __restrict__ vel, uint2* __restrict__ outh)
{
    int v = blockIdx.x * blockDim.x + threadIdx.x;
    if (v >= NVOX) return;
    const float s = 1.0f / 128.0f;
    outh[v] = pack_h(vel[v] * s, vel[NVOX + v] * s, vel[2 * NVOX + v] * s);
}

template <bool FIRST, bool LAST>
__global__ void __launch_bounds__(256) step_kernel(
    const float* __restrict__ fin,     // planar fp32 carry (velocity if FIRST)
    const uint2* __restrict__ hin,     // fp16 mirror (gather source)
    float* __restrict__ fout,          // planar fp32 (dst buffer or d_out)
    uint2* __restrict__ houth)         // fp16 mirror out (unused on last)
{
    const int v = blockIdx.x * blockDim.x + threadIdx.x;
    if (v >= NVOX) return;

    const float rf = c_rf;
    const float sx = rf * 0.5f * (float)(WW - 1);
    const float sy = rf * 0.5f * (float)(HH - 1);
    const float sz = rf * 0.5f * (float)(DD - 1);

    // voxel coords (W=128 power of two)
    const int x = v & (WW - 1);
    const int rest = v >> 7;
    const int y = rest % HH;
    const int z = rest / HH;

    // self flow: streaming loads (evict-first) — keep L2 for the mirrors.
    float fx = __ldcs(&fin[v]);
    float fy = __ldcs(&fin[NVOX + v]);
    float fz = __ldcs(&fin[2 * NVOX + v]);
    if (FIRST) {
        const float s = 1.0f / 128.0f;
        fx *= s; fy *= s; fz *= s;
    }

    float ix = fmaf(fx, sx, (float)x);
    float iy = fmaf(fy, sy, (float)y);
    float iz = fmaf(fz, sz, (float)z);
    ix = fminf(fmaxf(ix, 0.0f), (float)(WW - 1));
    iy = fminf(fmaxf(iy, 0.0f), (float)(HH - 1));
    iz = fminf(fmaxf(iz, 0.0f), (float)(DD - 1));

    const float x0f = floorf(ix), y0f = floorf(iy), z0f = floorf(iz);
    const float wx = ix - x0f, wy = iy - y0f, wz = iz - z0f;
    const int x0 = (int)x0f, y0 = (int)y0f, z0 = (int)z0f;
    const int x1 = min(x0 + 1, WW - 1);
    const int y1 = min(y0 + 1, HH - 1);
    const int z1 = min(z0 + 1, DD - 1);

    const int b00 = (z0 * HH + y0) * WW;
    const int b01 = (z0 * HH + y1) * WW;
    const int b10 = (z1 * HH + y0) * WW;
    const int b11 = (z1 * HH + y1) * WW;

    const float3 c000 = unpack_h(__ldg(&hin[b00 + x0]));
    const float3 c001 = unpack_h(__ldg(&hin[b00 + x1]));
    const float3 c010 = unpack_h(__ldg(&hin[b01 + x0]));
    const float3 c011 = unpack_h(__ldg(&hin[b01 + x1]));
    const float3 c100 = unpack_h(__ldg(&hin[b10 + x0]));
    const float3 c101 = unpack_h(__ldg(&hin[b10 + x1]));
    const float3 c110 = unpack_h(__ldg(&hin[b11 + x0]));
    const float3 c111 = unpack_h(__ldg(&hin[b11 + x1]));

    const float owx = 1.0f - wx, owy = 1.0f - wy, owz = 1.0f - wz;
    const float w00 = owz * owy, w01 = owz * wy, w10 = wz * owy, w11 = wz * wy;
    const float w000 = w00 * owx, w001 = w00 * wx;
    const float w010 = w01 * owx, w011 = w01 * wx;
    const float w100 = w10 * owx, w101 = w10 * wx;
    const float w110 = w11 * owx, w111 = w11 * wx;

    float rx = fx, ry = fy, rz = fz;
    rx = fmaf(w000, c000.x, rx); ry = fmaf(w000, c000.y, ry); rz = fmaf(w000, c000.z, rz);
    rx = fmaf(w001, c001.x, rx); ry = fmaf(w001, c001.y, ry); rz = fmaf(w001, c001.z, rz);
    rx = fmaf(w010, c010.x, rx); ry = fmaf(w010, c010.y, ry); rz = fmaf(w010, c010.z, rz);
    rx = fmaf(w011, c011.x, rx); ry = fmaf(w011, c011.y, ry); rz = fmaf(w011, c011.z, rz);
    rx = fmaf(w100, c100.x, rx); ry = fmaf(w100, c100.y, ry); rz = fmaf(w100, c100.z, rz);
    rx = fmaf(w101, c101.x, rx); ry = fmaf(w101, c101.y, ry); rz = fmaf(w101, c101.z, rz);
    rx = fmaf(w110, c110.x, rx); ry = fmaf(w110, c110.y, ry); rz = fmaf(w110, c110.z, rz);
    rx = fmaf(w111, c111.x, rx); ry = fmaf(w111, c111.y, ry); rz = fmaf(w111, c111.z, rz);

    if (LAST) {
        fout[v]            = rx;
        fout[NVOX + v]     = ry;
        fout[2 * NVOX + v] = rz;
    } else {
        __stcs(&fout[v],            rx);
        __stcs(&fout[NVOX + v],     ry);
        __stcs(&fout[2 * NVOX + v], rz);
        houth[v] = pack_h(rx, ry, rz);   // mirror: keep cached (hot data)
    }
}

extern "C" void kernel_launch(void* const* d_in, const int* in_sizes, int n_in,
                              void* d_out, int out_size) {
    (void)in_sizes; (void)n_in; (void)out_size;
    const float* velocity = (const float*)d_in[0];
    const float* rf       = (const float*)d_in[2];
    float* out            = (float*)d_out;

    float *fA, *fB;
    uint2 *hA, *hB;
    cudaGetSymbolAddress((void**)&fA, g_fA);
    cudaGetSymbolAddress((void**)&fB, g_fB);
    cudaGetSymbolAddress((void**)&hA, g_hA);
    cudaGetSymbolAddress((void**)&hB, g_hB);

    // rf (device scalar) -> __constant__, async D2D (graph-capturable)
    cudaMemcpyToSymbolAsync(c_rf, rf, sizeof(float), 0, cudaMemcpyDeviceToDevice);

    const int T = 256;
    const int G = NVOX / T;   // exact: 10240

    // mirror of flow0 only (first step reads velocity directly)
    convert_kernel<<<G, T>>>(velocity, hA);

    // step 1: fin = velocity (scaled in-kernel), mirror = hA, out -> fA/hB
    step_kernel<true, false><<<G, T>>>(velocity, hA, fA, hB);

    // steps 2..6
    float* src = fA;  uint2* hsrc = hB;
    float* dst = fB;  uint2* hdst = hA;
    for (int it = 0; it < 5; it++) {
        step_kernel<false, false><<<G, T>>>(src, hsrc, dst, hdst);
        float* t1 = src; src = dst; dst = t1;
        uint2* t2 = hsrc; hsrc = hdst; hdst = t2;
    }
    // step 7 -> d_out
    step_kernel<false, true><<<G, T>>>(src, hsrc, out, nullptr);
}